// round 16
// baseline (speedup 1.0000x reference)
#include <cuda_runtime.h>

// ---------------------------------------------------------------------------
// GCN 2-layer: out = A_hat(relu(A_hat(x@W1)+b1) @ W2) + b2
// CSR-gather design (R15 baseline, 211us). R16: gemm1 uses fma.rn.f32x2 with
// row-paired accumulators and SMEM-duplicated W pairs (all operands in SMEM).
// ---------------------------------------------------------------------------

#define MAX_N 100000
#define MAX_E 3200000
#define F_IN  512
#define HID   16
#define CLS   7
#define HID2  8     // padded h2 row stride

#define SCAN_B 1024
#define MAX_PART 128   // ceil(MAX_N / SCAN_B) = 98

typedef unsigned long long ull;

// Scratch (device globals: allocation-free rule).
__device__ __align__(16) int   g_degi  [MAX_N];
__device__ __align__(16) float g_dinv  [MAX_N];
__device__ __align__(16) int   g_rowptr[MAX_N + 1];
__device__ __align__(16) int   g_cursor[MAX_N];
__device__ __align__(16) int   g_part  [MAX_PART];
__device__ __align__(16) int   g_partpre[MAX_PART];
__device__ __align__(16) int2  g_csr   [MAX_E];        // {src, __float_as_int(w)}
__device__ __align__(16) float g_h     [MAX_N * HID];  // x @ W1
__device__ __align__(16) float g_hagg  [MAX_N * HID];  // aggregated layer-1
__device__ __align__(16) float g_h2    [MAX_N * HID2]; // relu(hagg+b1) @ W2, padded
__device__ int g_is64;                                  // edge_index dtype flag

// ---- f32x2 helpers ---------------------------------------------------------
__device__ __forceinline__ void ffma2(ull& d, ull a, ull b) {
    asm("fma.rn.f32x2 %0, %1, %2, %0;" : "+l"(d) : "l"(a), "l"(b));
}
__device__ __forceinline__ ull pack2(float lo, float hi) {
    ull r;
    asm("mov.b64 %0, {%1, %2};" : "=l"(r)
        : "r"(__float_as_uint(lo)), "r"(__float_as_uint(hi)));
    return r;
}
__device__ __forceinline__ void unpack2(ull v, float& lo, float& hi) {
    unsigned a, b;
    asm("mov.b64 {%0, %1}, %2;" : "=r"(a), "=r"(b) : "l"(v));
    lo = __uint_as_float(a);
    hi = __uint_as_float(b);
}

// ---------------------------------------------------------------------------
// dtype probe: int64 interpretation valid iff all sampled values in [0, n).
__global__ void k_detect(const void* __restrict__ ei, int n) {
    if (blockIdx.x == 0 && threadIdx.x == 0) {
        const long long* p = (const long long*)ei;
        int ok = 1;
        #pragma unroll 1
        for (int i = 0; i < 64; i++) {
            long long v = p[i];
            if (v < 0 || v >= (long long)n) { ok = 0; break; }
        }
        g_is64 = ok;
    }
}

__device__ __forceinline__ void edge_sd(const void* __restrict__ ei,
                                        int e, int E, int& s, int& d) {
    if (g_is64) {
        const long long* p = (const long long*)ei;
        s = (int)p[e];
        d = (int)p[e + E];
    } else {
        const int* p = (const int*)ei;
        s = p[e];
        d = p[e + E];
    }
}

// ---------------------------------------------------------------------------
__global__ void k_zero_deg(int n) {
    int i = blockIdx.x * blockDim.x + threadIdx.x;
    if (i < n) g_degi[i] = 0;
}

// int histogram of dst (scalar, 1 edge/thread — proven)
__global__ void k_deg(const void* __restrict__ ei, int E, int n) {
    int e = blockIdx.x * blockDim.x + threadIdx.x;
    if (e >= E) return;
    int d;
    if (g_is64) d = (int)((const long long*)ei)[e + E];
    else        d = ((const int*)ei)[e + E];
    if ((unsigned)d < (unsigned)n) atomicAdd(&g_degi[d], 1);
}

// ---------------------------------------------------------------------------
// Multi-block exclusive scan, phase 1: per-block (1024-chunk) sums.
__global__ void __launch_bounds__(SCAN_B) k_part(int n) {
    __shared__ int sd[SCAN_B];
    int t = threadIdx.x;
    int i = blockIdx.x * SCAN_B + t;
    sd[t] = (i < n) ? g_degi[i] : 0;
    __syncthreads();
    #pragma unroll
    for (int off = SCAN_B / 2; off > 0; off >>= 1) {
        if (t < off) sd[t] += sd[t + off];
        __syncthreads();
    }
    if (t == 0) g_part[blockIdx.x] = sd[0];
}

// Phase 2: single small block scans the partials (nb <= MAX_PART).
__global__ void __launch_bounds__(MAX_PART) k_scanpart(int nb, int n) {
    __shared__ int sd[MAX_PART];
    int t = threadIdx.x;
    int v = (t < nb) ? g_part[t] : 0;
    sd[t] = v;
    __syncthreads();
    #pragma unroll
    for (int off = 1; off < MAX_PART; off <<= 1) {
        int a = sd[t];
        int b = (t >= off) ? sd[t - off] : 0;
        __syncthreads();
        sd[t] = a + b;
        __syncthreads();
    }
    if (t < nb) g_partpre[t] = sd[t] - v;       // exclusive prefix
    if (t == MAX_PART - 1) g_rowptr[n] = sd[MAX_PART - 1];
}

// Phase 3: in-block exclusive scan + block offset; fused dinv.
__global__ void __launch_bounds__(SCAN_B) k_scanfinal(int n) {
    __shared__ int sd[SCAN_B];
    int t = threadIdx.x;
    int i = blockIdx.x * SCAN_B + t;
    int v = (i < n) ? g_degi[i] : 0;
    sd[t] = v;
    __syncthreads();
    #pragma unroll
    for (int off = 1; off < SCAN_B; off <<= 1) {
        int a = sd[t];
        int b = (t >= off) ? sd[t - off] : 0;
        __syncthreads();
        sd[t] = a + b;
        __syncthreads();
    }
    if (i < n) {
        int pos = g_partpre[blockIdx.x] + sd[t] - v;
        g_rowptr[i] = pos;
        g_cursor[i] = pos;
        g_dinv[i]   = rsqrtf((float)(v + 1));   // +1 self loop
    }
}

// ---------------------------------------------------------------------------
// Scatter edges into CSR slots (scalar, 1 edge/thread — proven).
__global__ void k_scatter(const void* __restrict__ ei, int E, int n) {
    int e = blockIdx.x * blockDim.x + threadIdx.x;
    if (e >= E) return;
    int s, d;
    edge_sd(ei, e, E, s, d);
    if ((unsigned)s >= (unsigned)n || (unsigned)d >= (unsigned)n) return;
    float w = g_dinv[s] * g_dinv[d];
    int pos = atomicAdd(&g_cursor[d], 1);
    if (pos < MAX_E) g_csr[pos] = make_int2(s, __float_as_int(w));
}

// ---------------------------------------------------------------------------
// GEMM1 v3: h = x @ W1   (M=n, K=512, N=16)
// 256 threads, 256 rows/block; thread handles 4 rows (rg+64i) x 4 cols as
// TWO f32x2 row-pairs: pair0 = rows (rg, rg+64), pair1 = (rg+128, rg+192).
// W pre-duplicated in SMEM as (w,w) pairs so a single LDS.128 yields two
// broadcast operands. FFMA count halves vs scalar version.
#define G1_ROWS 256
#define G1_KC   32
#define G1_XS_STRIDE 36   // 32 + 4 pad

__global__ void __launch_bounds__(256) k_gemm1(
    const float* __restrict__ x, const float* __restrict__ W1, int n)
{
    __shared__ __align__(16) float xs [G1_ROWS * G1_XS_STRIDE];  // 36 KB
    __shared__ __align__(16) float Wc2[G1_KC * 32];              // 4 KB (dup pairs)

    const int t    = threadIdx.x;
    const int rg   = t >> 2;
    const int cg   = t & 3;
    const int row0 = blockIdx.x * G1_ROWS;

    ull acc[2][4];   // [row-pair][col]
    #pragma unroll
    for (int p = 0; p < 2; p++)
        #pragma unroll
        for (int c = 0; c < 4; c++) acc[p][c] = 0ull;

    const float4* x4 = (const float4*)x;
    const float4* W4 = (const float4*)W1;

    for (int kc = 0; kc < F_IN / G1_KC; kc++) {
        __syncthreads();
        // x tile: 256 rows x 32 floats = 2048 float4, 8 per thread (coalesced).
        #pragma unroll
        for (int i = 0; i < 8; i++) {
            int idx = t + i * 256;
            int r   = idx >> 3;
            int q   = idx & 7;
            int gr  = row0 + r;
            float4 v = make_float4(0.f, 0.f, 0.f, 0.f);
            if (gr < n) v = x4[gr * (F_IN / 4) + kc * (G1_KC / 4) + q];
            *(float4*)&xs[r * G1_XS_STRIDE + q * 4] = v;
        }
        // W chunk, duplicated pairs: Wc2[k][2c..2c+1] = (w[k][c], w[k][c])
        if (t < 128) {
            float4 w = W4[kc * (G1_KC * HID / 4) + t];
            int k  = t >> 2;
            int c4 = (t & 3) * 8;
            *(float4*)&Wc2[k * 32 + c4 + 0] = make_float4(w.x, w.x, w.y, w.y);
            *(float4*)&Wc2[k * 32 + c4 + 4] = make_float4(w.z, w.z, w.w, w.w);
        }
        __syncthreads();

        #pragma unroll
        for (int k4 = 0; k4 < G1_KC / 4; k4++) {
            const int k = k4 * 4;
            float4 xv0 = *(const float4*)&xs[(rg +   0) * G1_XS_STRIDE + k];
            float4 xv1 = *(const float4*)&xs[(rg +  64) * G1_XS_STRIDE + k];
            float4 xv2 = *(const float4*)&xs[(rg + 128) * G1_XS_STRIDE + k];
            float4 xv3 = *(const float4*)&xs[(rg + 192) * G1_XS_STRIDE + k];
            #pragma unroll
            for (int kk = 0; kk < 4; kk++) {
                float4 wA = *(const float4*)&Wc2[(k + kk) * 32 + cg * 8 + 0];
                float4 wB = *(const float4*)&Wc2[(k + kk) * 32 + cg * 8 + 4];
                ull w0 = ((const ull*)&wA)[0];  // (c0,c0)
                ull w1 = ((const ull*)&wA)[1];  // (c1,c1)
                ull w2 = ((const ull*)&wB)[0];  // (c2,c2)
                ull w3 = ((const ull*)&wB)[1];  // (c3,c3)
                float a0 = (kk == 0) ? xv0.x : (kk == 1) ? xv0.y : (kk == 2) ? xv0.z : xv0.w;
                float a1 = (kk == 0) ? xv1.x : (kk == 1) ? xv1.y : (kk == 2) ? xv1.z : xv1.w;
                float a2 = (kk == 0) ? xv2.x : (kk == 1) ? xv2.y : (kk == 2) ? xv2.z : xv2.w;
                float a3 = (kk == 0) ? xv3.x : (kk == 1) ? xv3.y : (kk == 2) ? xv3.z : xv3.w;
                ull p0 = pack2(a0, a1);
                ull p1 = pack2(a2, a3);
                ffma2(acc[0][0], p0, w0); ffma2(acc[0][1], p0, w1);
                ffma2(acc[0][2], p0, w2); ffma2(acc[0][3], p0, w3);
                ffma2(acc[1][0], p1, w0); ffma2(acc[1][1], p1, w1);
                ffma2(acc[1][2], p1, w2); ffma2(acc[1][3], p1, w3);
            }
        }
    }

    // Epilogue: pair p, lo half = row rg+128p, hi half = row rg+64+128p
    #pragma unroll
    for (int p = 0; p < 2; p++) {
        float lo0, hi0, lo1, hi1, lo2, hi2, lo3, hi3;
        unpack2(acc[p][0], lo0, hi0);
        unpack2(acc[p][1], lo1, hi1);
        unpack2(acc[p][2], lo2, hi2);
        unpack2(acc[p][3], lo3, hi3);
        int rA = row0 + rg + 128 * p;
        int rB = rA + 64;
        if (rA < n)
            *(float4*)&g_h[rA * HID + cg * 4] = make_float4(lo0, lo1, lo2, lo3);
        if (rB < n)
            *(float4*)&g_h[rB * HID + cg * 4] = make_float4(hi0, hi1, hi2, hi3);
    }
}

// ---------------------------------------------------------------------------
// Layer-1 aggregation (gather, no atomics): 4 lanes/node, float4 per lane.
__global__ void __launch_bounds__(256) k_agg1(int n)
{
    int id   = blockIdx.x * blockDim.x + threadIdx.x;
    int node = id >> 2;
    if (node >= n) return;
    int q = (id & 3) * 4;   // feature group: 0,4,8,12

    int j   = g_rowptr[node];
    int end = g_rowptr[node + 1];

    float4 a0 = make_float4(0.f, 0.f, 0.f, 0.f);
    float4 a1 = make_float4(0.f, 0.f, 0.f, 0.f);
    for (; j + 1 < end; j += 2) {
        int2 r0 = g_csr[j];
        int2 r1 = g_csr[j + 1];
        float  w0 = __int_as_float(r0.y);
        float  w1 = __int_as_float(r1.y);
        float4 h0 = *(const float4*)&g_h[r0.x * HID + q];
        float4 h1 = *(const float4*)&g_h[r1.x * HID + q];
        a0.x = fmaf(h0.x, w0, a0.x); a0.y = fmaf(h0.y, w0, a0.y);
        a0.z = fmaf(h0.z, w0, a0.z); a0.w = fmaf(h0.w, w0, a0.w);
        a1.x = fmaf(h1.x, w1, a1.x); a1.y = fmaf(h1.y, w1, a1.y);
        a1.z = fmaf(h1.z, w1, a1.z); a1.w = fmaf(h1.w, w1, a1.w);
    }
    if (j < end) {
        int2 r = g_csr[j];
        float  w = __int_as_float(r.y);
        float4 h = *(const float4*)&g_h[r.x * HID + q];
        a0.x = fmaf(h.x, w, a0.x); a0.y = fmaf(h.y, w, a0.y);
        a0.z = fmaf(h.z, w, a0.z); a0.w = fmaf(h.w, w, a0.w);
    }

    float di = g_dinv[node];
    float sw = di * di;
    float4 hv = *(const float4*)&g_h[node * HID + q];
    float4 r;
    r.x = a0.x + a1.x + hv.x * sw;
    r.y = a0.y + a1.y + hv.y * sw;
    r.z = a0.z + a1.z + hv.z * sw;
    r.w = a0.w + a1.w + hv.w * sw;
    *(float4*)&g_hagg[node * HID + q] = r;
}

// ---------------------------------------------------------------------------
// GEMM2: h2 = relu(hagg + b1) @ W2  (h2 stored with padded stride HID2=8)
__global__ void __launch_bounds__(256) k_gemm2(
    const float* __restrict__ b1, const float* __restrict__ W2, int n)
{
    __shared__ float W2s[HID * CLS];
    __shared__ float b1s[HID];
    int t = threadIdx.x;
    if (t < HID * CLS) W2s[t] = W2[t];
    if (t < HID)       b1s[t] = b1[t];
    __syncthreads();

    int i = blockIdx.x * blockDim.x + t;
    if (i >= n) return;

    float v[HID];
    #pragma unroll
    for (int q = 0; q < 4; q++) {
        float4 hv = *(const float4*)&g_hagg[i * HID + q * 4];
        v[q * 4 + 0] = fmaxf(hv.x + b1s[q * 4 + 0], 0.0f);
        v[q * 4 + 1] = fmaxf(hv.y + b1s[q * 4 + 1], 0.0f);
        v[q * 4 + 2] = fmaxf(hv.z + b1s[q * 4 + 2], 0.0f);
        v[q * 4 + 3] = fmaxf(hv.w + b1s[q * 4 + 3], 0.0f);
    }

    float o[8];
    #pragma unroll
    for (int c2 = 0; c2 < 8; c2++) o[c2] = 0.0f;
    #pragma unroll
    for (int c = 0; c < HID; c++) {
        float xv = v[c];
        #pragma unroll
        for (int c2 = 0; c2 < CLS; c2++) o[c2] += xv * W2s[c * CLS + c2];
    }

    *(float4*)&g_h2[i * HID2 + 0] = make_float4(o[0], o[1], o[2], o[3]);
    *(float4*)&g_h2[i * HID2 + 4] = make_float4(o[4], o[5], o[6], 0.0f);
}

// ---------------------------------------------------------------------------
// Layer-2 aggregation (gather): 2 lanes/node, float4 per lane (padded h2).
__global__ void __launch_bounds__(256) k_agg2(
    const float* __restrict__ b2, float* __restrict__ out, int n)
{
    int id   = blockIdx.x * blockDim.x + threadIdx.x;
    int node = id >> 1;
    if (node >= n) return;
    int q = (id & 1) * 4;   // 0 or 4

    int j   = g_rowptr[node];
    int end = g_rowptr[node + 1];

    float4 a0 = make_float4(0.f, 0.f, 0.f, 0.f);
    float4 a1 = make_float4(0.f, 0.f, 0.f, 0.f);
    for (; j + 1 < end; j += 2) {
        int2 r0 = g_csr[j];
        int2 r1 = g_csr[j + 1];
        float  w0 = __int_as_float(r0.y);
        float  w1 = __int_as_float(r1.y);
        float4 h0 = *(const float4*)&g_h2[r0.x * HID2 + q];
        float4 h1 = *(const float4*)&g_h2[r1.x * HID2 + q];
        a0.x = fmaf(h0.x, w0, a0.x); a0.y = fmaf(h0.y, w0, a0.y);
        a0.z = fmaf(h0.z, w0, a0.z); a0.w = fmaf(h0.w, w0, a0.w);
        a1.x = fmaf(h1.x, w1, a1.x); a1.y = fmaf(h1.y, w1, a1.y);
        a1.z = fmaf(h1.z, w1, a1.z); a1.w = fmaf(h1.w, w1, a1.w);
    }
    if (j < end) {
        int2 r = g_csr[j];
        float  w = __int_as_float(r.y);
        float4 h = *(const float4*)&g_h2[r.x * HID2 + q];
        a0.x = fmaf(h.x, w, a0.x); a0.y = fmaf(h.y, w, a0.y);
        a0.z = fmaf(h.z, w, a0.z); a0.w = fmaf(h.w, w, a0.w);
    }

    float di = g_dinv[node];
    float sw = di * di;
    float4 hv = *(const float4*)&g_h2[node * HID2 + q];
    float r0 = a0.x + a1.x + hv.x * sw;
    float r1 = a0.y + a1.y + hv.y * sw;
    float r2 = a0.z + a1.z + hv.z * sw;
    float r3 = a0.w + a1.w + hv.w * sw;

    float* op = out + node * CLS;
    if (q == 0) {
        op[0] = r0 + b2[0];
        op[1] = r1 + b2[1];
        op[2] = r2 + b2[2];
        op[3] = r3 + b2[3];
    } else {
        op[4] = r0 + b2[4];
        op[5] = r1 + b2[5];
        op[6] = r2 + b2[6];
    }
}

// ---------------------------------------------------------------------------
extern "C" void kernel_launch(void* const* d_in, const int* in_sizes, int n_in,
                              void* d_out, int out_size)
{
    // ---- identify inputs by element count ----
    int ix = -1, ie = -1, iw1 = -1, ib1 = -1, iw2 = -1, ib2 = -1;
    for (int i = 0; i < n_in; i++)
        if (ix < 0 || in_sizes[i] > in_sizes[ix]) ix = i;
    for (int i = 0; i < n_in; i++) {
        if (i == ix) continue;
        if (ie < 0 || in_sizes[i] > in_sizes[ie]) ie = i;
    }
    for (int i = 0; i < n_in; i++) {
        if (i == ix || i == ie) continue;
        if (in_sizes[i] == F_IN * HID) iw1 = i;
        else if (in_sizes[i] == HID * CLS) iw2 = i;
        else if (in_sizes[i] == HID) ib1 = i;
        else if (in_sizes[i] == CLS) ib2 = i;
    }
    if (ix < 0 || ie < 0 || iw1 < 0 || ib1 < 0 || iw2 < 0 || ib2 < 0) {
        ix = 0; ie = 1; iw1 = 2; ib1 = 3; iw2 = 4; ib2 = 5;
    }

    const float* x  = (const float*)d_in[ix];
    const void*  ei = d_in[ie];
    const float* W1 = (const float*)d_in[iw1];
    const float* b1 = (const float*)d_in[ib1];
    const float* W2 = (const float*)d_in[iw2];
    const float* b2 = (const float*)d_in[ib2];
    float* out = (float*)d_out;

    const int n = in_sizes[ix] / F_IN;   // 100000
    const int E = in_sizes[ie] / 2;      // 3200000

    const int TB = 256;
    const int nb = (n + SCAN_B - 1) / SCAN_B;   // 98

    // gemm1 kept at launch slot 4 (the profiler captures the 4th launch).
    k_detect<<<1, 32>>>(ei, n);                                   // 1
    k_zero_deg<<<(n + TB - 1) / TB, TB>>>(n);                     // 2
    k_deg<<<(E + TB - 1) / TB, TB>>>(ei, E, n);                   // 3
    k_gemm1<<<(n + G1_ROWS - 1) / G1_ROWS, 256>>>(x, W1, n);      // 4  <- profiled
    k_part<<<nb, SCAN_B>>>(n);                                    // 5
    k_scanpart<<<1, MAX_PART>>>(nb, n);                           // 6
    k_scanfinal<<<nb, SCAN_B>>>(n);                               // 7
    k_scatter<<<(E + TB - 1) / TB, TB>>>(ei, E, n);               // 8

    // layer 1 aggregation
    {
        long long work = (long long)n * 4;
        k_agg1<<<(int)((work + TB - 1) / TB), TB>>>(n);           // 9
    }

    // layer 2
    k_gemm2<<<(n + TB - 1) / TB, TB>>>(b1, W2, n);                // 10
    {
        long long work = (long long)n * 2;
        k_agg2<<<(int)((work + TB - 1) / TB), TB>>>(b2, out, n);  // 11
    }
}